// round 15
// baseline (speedup 1.0000x reference)
#include <cuda_runtime.h>

#define NU 100000
#define NI 50000
#define NN 150000
#define DD 64
#define EG 3200000
#define EU_ 1600000
#define EI_ 800000

typedef unsigned long long ull;

// ---------------- device scratch ----------------
__device__ float g_cur[NN * DD];    // cur0 = emb
__device__ float g_curB[NN * DD];   // cur1 after layer 1
__device__ float g_gnn[NN * DD];
__device__ float g_int[NN * DD];
__device__ float g_z[NN * 2 * DD];
__device__ float g_wsum[4];

// CSR for G
__device__ int    g_cntG[NN];
__device__ int    g_curG[NN];
__device__ int    g_rptrG[NN + 1];
__device__ float2 g_epayG[EG];

// CSR + degrees for HAN
#define HN (2 * NU + 2 * NI)
__device__ int g_dout[HN];
__device__ int g_din[HN];
__device__ int g_curH[HN];
__device__ int g_rptrH[2 * (NU + 1) + 2 * (NI + 1)];
__device__ int g_hpay[2 * EU_ + 2 * EI_];

// block-sum scratch for parallel scans
#define NB_G 147
#define NB_HU 98
#define NB_HI 49
__device__ int g_bsumG[NB_G];
__device__ int g_bsumH[4 * NB_HU];

// f32x2 packed math (sm_100+)
__device__ __forceinline__ ull pk2(float a) {
    ull r;
    asm("mov.b64 %0, {%1, %1};" : "=l"(r) : "f"(a));
    return r;
}
__device__ __forceinline__ ull pack2(float lo, float hi) {
    ull r;
    asm("mov.b64 %0, {%1, %2};" : "=l"(r) : "f"(lo), "f"(hi));
    return r;
}
__device__ __forceinline__ void fma2(ull& d, ull a, ull b) {
    asm("fma.rn.f32x2 %0, %1, %2, %0;" : "+l"(d) : "l"(a), "l"(b));
}
__device__ __forceinline__ float2 up2(ull v) {
    float2 f;
    asm("mov.b64 {%0, %1}, %2;" : "=f"(f.x), "=f"(f.y) : "l"(v));
    return f;
}

// ---------------- zero counters ----------------
__global__ void __launch_bounds__(256) k_zero_cnt() {
    unsigned i = blockIdx.x * 256u + threadIdx.x;
    if (i < NN) { g_cntG[i] = 0; g_curG[i] = 0; }
    if (i < HN) { g_dout[i] = 0; g_din[i] = 0; g_curH[i] = 0; }
    if (i < 4u) g_wsum[i] = 0.f;
}

// ---------------- init (cur0 only) ----------------
__global__ void __launch_bounds__(256) k_init(const float* __restrict__ fu,
                                              const float* __restrict__ fi) {
    unsigned i = blockIdx.x * 256u + threadIdx.x;
    if (i < NU * DD) g_cur[i] = fu[i];
    else if (i < NN * DD) g_cur[i] = fi[i - NU * DD];
}

// ---------------- histograms ----------------
__global__ void __launch_bounds__(256) k_histG(const int* __restrict__ G) {
    unsigned e = blockIdx.x * 256u + threadIdx.x;
    if (e >= EG) return;
    atomicAdd(&g_cntG[__ldg(G + e)], 1);
}

__global__ void __launch_bounds__(256) k_histH(const int* __restrict__ edges, int E2,
                                               int n, int base) {
    unsigned t = blockIdx.x * 256u + threadIdx.x;
    if (t >= 2u * (unsigned)E2) return;
    int m = (t >= (unsigned)E2) ? 1 : 0;
    int e = (int)t - m * E2;
    int src = __ldg(edges + (size_t)m * 2 * E2 + e);
    int dst = __ldg(edges + (size_t)m * 2 * E2 + E2 + e);
    atomicAdd(&g_dout[base + m * n + src], 1);
    atomicAdd(&g_din[base + m * n + dst], 1);
}

// ---------------- parallel scans ----------------
__device__ __forceinline__ int blockscan_1024(int v, int* ws) {
    const int tid = threadIdx.x, lane = tid & 31, wid = tid >> 5;
    int x = v;
#pragma unroll
    for (int off = 1; off < 32; off <<= 1) {
        int y = __shfl_up_sync(0xffffffffu, x, off);
        if (lane >= off) x += y;
    }
    if (lane == 31) ws[wid] = x;
    __syncthreads();
    if (wid == 0) {
        int s = ws[lane];
#pragma unroll
        for (int off = 1; off < 32; off <<= 1) {
            int y = __shfl_up_sync(0xffffffffu, s, off);
            if (lane >= off) s += y;
        }
        ws[lane] = s;
    }
    __syncthreads();
    return x - v + (wid > 0 ? ws[wid - 1] : 0);
}

__global__ void __launch_bounds__(1024) k_scanG1() {
    __shared__ int ws[32];
    int i = blockIdx.x * 1024 + threadIdx.x;
    int v = (i < NN) ? g_cntG[i] : 0;
    int excl = blockscan_1024(v, ws);
    if (i < NN) g_rptrG[i] = excl;
    if (threadIdx.x == 0) g_bsumG[blockIdx.x] = ws[31];
}

__global__ void __launch_bounds__(32) k_scanG2() {
    int lane = threadIdx.x;
    int carry = 0;
    for (int base = 0; base < NB_G; base += 32) {
        int idx = base + lane;
        int v = (idx < NB_G) ? g_bsumG[idx] : 0;
        int x = v;
#pragma unroll
        for (int off = 1; off < 32; off <<= 1) {
            int y = __shfl_up_sync(0xffffffffu, x, off);
            if (lane >= off) x += y;
        }
        if (idx < NB_G) g_bsumG[idx] = x - v + carry;
        carry += __shfl_sync(0xffffffffu, x, 31);
    }
    if (lane == 0) g_rptrG[NN] = carry;
}

__global__ void __launch_bounds__(1024) k_scanG3() {
    int i = blockIdx.x * 1024 + threadIdx.x;
    if (i < NN) g_rptrG[i] += g_bsumG[blockIdx.x];
}

__device__ __forceinline__ void hseg_decode(int b, int& seg, int& lb, int& n,
                                            const int*& cnt, int*& rptr) {
    if (b < NB_HU)           { seg = 0; lb = b; }
    else if (b < 2 * NB_HU)  { seg = 1; lb = b - NB_HU; }
    else if (b < 2 * NB_HU + NB_HI) { seg = 2; lb = b - 2 * NB_HU; }
    else                     { seg = 3; lb = b - 2 * NB_HU - NB_HI; }
    n = (seg < 2) ? NU : NI;
    cnt = g_din + (seg == 0 ? 0 : seg == 1 ? NU : seg == 2 ? 2 * NU : 2 * NU + NI);
    rptr = g_rptrH + (seg == 0 ? 0 : seg == 1 ? (NU + 1)
                      : seg == 2 ? 2 * (NU + 1) : 2 * (NU + 1) + (NI + 1));
}

__global__ void __launch_bounds__(1024) k_scanH1() {
    __shared__ int ws[32];
    int seg, lb, n; const int* cnt; int* rptr;
    hseg_decode(blockIdx.x, seg, lb, n, cnt, rptr);
    int i = lb * 1024 + threadIdx.x;
    int v = (i < n) ? cnt[i] : 0;
    int excl = blockscan_1024(v, ws);
    if (i < n) rptr[i] = excl;
    if (threadIdx.x == 0) g_bsumH[seg * NB_HU + lb] = ws[31];
}

__global__ void __launch_bounds__(128) k_scanH2() {
    int lane = threadIdx.x & 31, seg = threadIdx.x >> 5;
    int nb = (seg < 2) ? NB_HU : NB_HI;
    int n = (seg < 2) ? NU : NI;
    int* rptr = g_rptrH + (seg == 0 ? 0 : seg == 1 ? (NU + 1)
                           : seg == 2 ? 2 * (NU + 1) : 2 * (NU + 1) + (NI + 1));
    int* bs = g_bsumH + seg * NB_HU;
    int carry = 0;
    for (int base = 0; base < nb; base += 32) {
        int idx = base + lane;
        int v = (idx < nb) ? bs[idx] : 0;
        int x = v;
#pragma unroll
        for (int off = 1; off < 32; off <<= 1) {
            int y = __shfl_up_sync(0xffffffffu, x, off);
            if (lane >= off) x += y;
        }
        if (idx < nb) bs[idx] = x - v + carry;
        carry += __shfl_sync(0xffffffffu, x, 31);
    }
    if (lane == 0) rptr[n] = carry;
}

__global__ void __launch_bounds__(1024) k_scanH3() {
    int seg, lb, n; const int* cnt; int* rptr;
    hseg_decode(blockIdx.x, seg, lb, n, cnt, rptr);
    int i = lb * 1024 + threadIdx.x;
    if (i < n) rptr[i] += g_bsumH[seg * NB_HU + lb];
}

// ---------------- CSR fill ----------------
__global__ void __launch_bounds__(256) k_fillG(const int* __restrict__ G,
                                               const float* __restrict__ gv) {
    unsigned e = blockIdx.x * 256u + threadIdx.x;
    if (e >= EG) return;
    int row = __ldg(G + e);
    int col = __ldg(G + EG + e);
    float v = __ldg(gv + e);
    int pos = g_rptrG[row] + atomicAdd(&g_curG[row], 1);
    g_epayG[pos] = make_float2(__int_as_float(col), v);
}

__global__ void __launch_bounds__(256) k_fillH(const int* __restrict__ edges, int E2,
                                               int n, int base, int rbase, int paybase) {
    unsigned t = blockIdx.x * 256u + threadIdx.x;
    if (t >= 2u * (unsigned)E2) return;
    int m = (t >= (unsigned)E2) ? 1 : 0;
    int e = (int)t - m * E2;
    int src = __ldg(edges + (size_t)m * 2 * E2 + e);
    int dst = __ldg(edges + (size_t)m * 2 * E2 + E2 + e);
    const int* rptr = g_rptrH + rbase + m * (n + 1);
    int pos = rptr[dst] + atomicAdd(&g_curH[base + m * n + dst], 1);
    g_hpay[paybase + m * E2 + pos] = src;
}

// ---------------- DCCF: CSR SpMM (src-parameterized) ----------------
__global__ void __launch_bounds__(256) k_spmm_csr(const float* __restrict__ src) {
    unsigned t = blockIdx.x * 256u + threadIdx.x;
    unsigned r = t >> 4;
    unsigned c = t & 15u;
    if (r >= NN) return;
    int s = g_rptrG[r], e = g_rptrG[r + 1];
    float4 acc = make_float4(0.f, 0.f, 0.f, 0.f);
    int i = s;
    for (; i + 2 <= e; i += 2) {
        float2 p0 = __ldg(&g_epayG[i]);
        float2 p1 = __ldg(&g_epayG[i + 1]);
        int c0 = __float_as_int(p0.x), c1 = __float_as_int(p1.x);
        float4 x0 = *(const float4*)(src + (size_t)c0 * DD + c * 4);
        float4 x1 = *(const float4*)(src + (size_t)c1 * DD + c * 4);
        acc.x += p0.y * x0.x + p1.y * x1.x;
        acc.y += p0.y * x0.y + p1.y * x1.y;
        acc.z += p0.y * x0.z + p1.y * x1.z;
        acc.w += p0.y * x0.w + p1.y * x1.w;
    }
    if (i < e) {
        float2 p0 = __ldg(&g_epayG[i]);
        int c0 = __float_as_int(p0.x);
        float4 x0 = *(const float4*)(src + (size_t)c0 * DD + c * 4);
        acc.x += p0.y * x0.x; acc.y += p0.y * x0.y;
        acc.z += p0.y * x0.z; acc.w += p0.y * x0.w;
    }
    *(float4*)(g_gnn + (size_t)r * DD + c * 4) = acc;
}

// ---------------- DCCF: intent projection — pre-splatted W, zero pk2 in loops ----------------
// smem bytes:
//   Wsp  [0 .. 67584)        ulonglong2 {pk2(W[2L][j]), pk2(W[2L+1][j])} at j*33+L
//   uT2  [67584 .. 83968)    8 warps * 256 u64
//   pT2  [83968 .. 116736)   8 warps * 512 u64
#define INTENT_SMEM 116736
#define IT_THREADS 256
#define IT_ROWS_PER_BLOCK 64

__global__ void __launch_bounds__(IT_THREADS)
k_intent(const float* __restrict__ Wu, const float* __restrict__ Wi,
         const float* __restrict__ srcu, const float* __restrict__ srci) {
    extern __shared__ char smb[];
    ulonglong2* Wsp = (ulonglong2*)smb;
    const int tid = threadIdx.x, w = tid >> 5, lane = tid & 31;

    ull* uT2 = (ull*)(smb + 67584) + w * 256;
    ull* pT2 = (ull*)(smb + 83968) + w * 512;

    const int UB = (NU + IT_ROWS_PER_BLOCK - 1) / IT_ROWS_PER_BLOCK;
    const bool isUser = (int)blockIdx.x < UB;
    const float* Wg = isUser ? Wu : Wi;
    const int rowbase = isUser ? (int)blockIdx.x * IT_ROWS_PER_BLOCK
                               : NU + ((int)blockIdx.x - UB) * IT_ROWS_PER_BLOCK;
    const int rowlim = isUser ? NU : NN;
    const float* srcp = isUser ? srcu : srci;
    const int srcoff = isUser ? 0 : NU;

    for (int t = tid; t < 4096; t += IT_THREADS) {
        int L = t >> 7, j = t & 127;
        float a = Wg[(2 * L) * 128 + j];
        float b = Wg[(2 * L + 1) * 128 + j];
        Wsp[j * 33 + L] = make_ulonglong2(pk2(a), pk2(b));
    }
    __syncthreads();

    const int r0 = rowbase + w * 8;

    for (int t = lane; t < 256; t += 32) {
        int rho = t >> 6, k = t & 63;
        int ra = r0 + 2 * rho, rb = ra + 1;
        float xa = (ra < rowlim) ? srcp[(size_t)(ra - srcoff) * DD + k] : 0.f;
        float xb = (rb < rowlim) ? srcp[(size_t)(rb - srcoff) * DD + k] : 0.f;
        uT2[rho * 64 + k] = pack2(xa, xb);
    }
    __syncwarp();

    // ---- pass 1: scores = u @ W ----
    ull acc[4][4];
#pragma unroll
    for (int a = 0; a < 4; a++) { acc[a][0] = acc[a][1] = acc[a][2] = acc[a][3] = 0ull; }

    const ulonglong2* uT2v = (const ulonglong2*)uT2;
#pragma unroll 4
    for (int L = 0; L < 32; L++) {
        ulonglong2 W0 = Wsp[(lane +  0) * 33 + L];
        ulonglong2 W1 = Wsp[(lane + 32) * 33 + L];
        ulonglong2 W2 = Wsp[(lane + 64) * 33 + L];
        ulonglong2 W3 = Wsp[(lane + 96) * 33 + L];
#pragma unroll
        for (int rho = 0; rho < 4; rho++) {
            ulonglong2 up = uT2v[rho * 32 + L];
            fma2(acc[rho][0], W0.x, up.x); fma2(acc[rho][0], W0.y, up.y);
            fma2(acc[rho][1], W1.x, up.x); fma2(acc[rho][1], W1.y, up.y);
            fma2(acc[rho][2], W2.x, up.x); fma2(acc[rho][2], W2.y, up.y);
            fma2(acc[rho][3], W3.x, up.x); fma2(acc[rho][3], W3.y, up.y);
        }
    }

    // ---- softmax per row (both parities), write pT2 ----
#pragma unroll
    for (int rho = 0; rho < 4; rho++) {
        float2 a0 = up2(acc[rho][0]), a1 = up2(acc[rho][1]);
        float2 a2 = up2(acc[rho][2]), a3 = up2(acc[rho][3]);
        float ml = fmaxf(fmaxf(a0.x, a1.x), fmaxf(a2.x, a3.x));
        float mh = fmaxf(fmaxf(a0.y, a1.y), fmaxf(a2.y, a3.y));
#pragma unroll
        for (int off = 16; off; off >>= 1) {
            ml = fmaxf(ml, __shfl_xor_sync(0xffffffffu, ml, off));
            mh = fmaxf(mh, __shfl_xor_sync(0xffffffffu, mh, off));
        }
        float el0 = __expf(a0.x - ml), el1 = __expf(a1.x - ml);
        float el2 = __expf(a2.x - ml), el3 = __expf(a3.x - ml);
        float eh0 = __expf(a0.y - mh), eh1 = __expf(a1.y - mh);
        float eh2 = __expf(a2.y - mh), eh3 = __expf(a3.y - mh);
        float sl = el0 + el1 + el2 + el3;
        float sh = eh0 + eh1 + eh2 + eh3;
#pragma unroll
        for (int off = 16; off; off >>= 1) {
            sl += __shfl_xor_sync(0xffffffffu, sl, off);
            sh += __shfl_xor_sync(0xffffffffu, sh, off);
        }
        float il = 1.f / sl, ih = 1.f / sh;
        pT2[rho * 128 + lane +  0] = pack2(el0 * il, eh0 * ih);
        pT2[rho * 128 + lane + 32] = pack2(el1 * il, eh1 * ih);
        pT2[rho * 128 + lane + 64] = pack2(el2 * il, eh2 * ih);
        pT2[rho * 128 + lane + 96] = pack2(el3 * il, eh3 * ih);
    }
    __syncwarp();

    // ---- pass 2: out = p @ W^T (same Wsp elements: lane owns d=2lane,2lane+1) ----
    ull acc2[4][2];
#pragma unroll
    for (int a = 0; a < 4; a++) { acc2[a][0] = 0ull; acc2[a][1] = 0ull; }

    const ulonglong2* pT2v = (const ulonglong2*)pT2;
#pragma unroll 2
    for (int j4 = 0; j4 < 32; j4++) {
        ulonglong2 P0a = pT2v[0 * 64 + 2 * j4], P0b = pT2v[0 * 64 + 2 * j4 + 1];
        ulonglong2 P1a = pT2v[1 * 64 + 2 * j4], P1b = pT2v[1 * 64 + 2 * j4 + 1];
        ulonglong2 P2a = pT2v[2 * 64 + 2 * j4], P2b = pT2v[2 * 64 + 2 * j4 + 1];
        ulonglong2 P3a = pT2v[3 * 64 + 2 * j4], P3b = pT2v[3 * 64 + 2 * j4 + 1];
#define P2J(JJ, PW)                                                     \
        {                                                               \
            ulonglong2 wt = Wsp[(4 * j4 + JJ) * 33 + lane];             \
            fma2(acc2[0][0], wt.x, P0##PW); fma2(acc2[0][1], wt.y, P0##PW); \
            fma2(acc2[1][0], wt.x, P1##PW); fma2(acc2[1][1], wt.y, P1##PW); \
            fma2(acc2[2][0], wt.x, P2##PW); fma2(acc2[2][1], wt.y, P2##PW); \
            fma2(acc2[3][0], wt.x, P3##PW); fma2(acc2[3][1], wt.y, P3##PW); \
        }
        P2J(0, a.x) P2J(1, a.y) P2J(2, b.x) P2J(3, b.y)
#undef P2J
    }

#pragma unroll
    for (int rho = 0; rho < 4; rho++) {
        float2 o0 = up2(acc2[rho][0]);
        float2 o1 = up2(acc2[rho][1]);
#pragma unroll
        for (int par = 0; par < 2; par++) {
            int r = r0 + 2 * rho + par;
            if (r >= rowlim) continue;
            float oa = par ? o0.y : o0.x;
            float ob = par ? o1.y : o1.x;
            *(float2*)(g_int + (size_t)r * DD + lane * 2) = make_float2(oa, ob);
        }
    }
}

// ---------------- DCCF: layer-1 epilogue: curB = gnn + int + cur0 ----------------
__global__ void __launch_bounds__(256) k_epi1() {
    unsigned i = blockIdx.x * 256u + threadIdx.x;
    if (i >= (unsigned)(NN * DD / 4)) return;
    float4 gn = ((const float4*)g_gnn)[i];
    float4 iv = ((const float4*)g_int)[i];
    float4 cu = ((const float4*)g_cur)[i];
    float4 nv;
    nv.x = gn.x + iv.x + cu.x;
    nv.y = gn.y + iv.y + cu.y;
    nv.z = gn.z + iv.z + cu.z;
    nv.w = gn.w + iv.w + cu.w;
    ((float4*)g_curB)[i] = nv;
}

// ---------------- HAN: CSR gather ----------------
__global__ void __launch_bounds__(256) k_hgather(const float* __restrict__ feat, int E2,
                                                 int n, int base, int rbase, int paybase,
                                                 int zbase) {
    unsigned t = blockIdx.x * 256u + threadIdx.x;
    unsigned idx = t >> 4;
    unsigned c = t & 15u;
    if (idx >= 2u * (unsigned)n) return;
    int m = (idx >= (unsigned)n) ? 1 : 0;
    int node = (int)idx - m * n;
    const int* rptr = g_rptrH + rbase + m * (n + 1);
    int s = rptr[node], e = rptr[node + 1];
    const int* pay = g_hpay + paybase + m * E2;
    const int* dout = g_dout + base + m * n;
    float4 acc = make_float4(0.f, 0.f, 0.f, 0.f);
    int i = s;
    for (; i + 2 <= e; i += 2) {
        int s0 = __ldg(pay + i), s1 = __ldg(pay + i + 1);
        float w0 = rsqrtf((float)__ldg(dout + s0));
        float w1 = rsqrtf((float)__ldg(dout + s1));
        float4 x0 = *(const float4*)(feat + (size_t)s0 * DD + c * 4);
        float4 x1 = *(const float4*)(feat + (size_t)s1 * DD + c * 4);
        acc.x += w0 * x0.x + w1 * x1.x;
        acc.y += w0 * x0.y + w1 * x1.y;
        acc.z += w0 * x0.z + w1 * x1.z;
        acc.w += w0 * x0.w + w1 * x1.w;
    }
    if (i < e) {
        int s0 = __ldg(pay + i);
        float w0 = rsqrtf((float)__ldg(dout + s0));
        float4 x0 = *(const float4*)(feat + (size_t)s0 * DD + c * 4);
        acc.x += w0 * x0.x; acc.y += w0 * x0.y;
        acc.z += w0 * x0.z; acc.w += w0 * x0.w;
    }
    float din = (float)(e - s);
    float sc = (din > 0.f) ? rsqrtf(din) : 0.f;
    *(float4*)(g_z + (size_t)zbase + ((size_t)node * 2 + m) * DD + c * 4) =
        make_float4(acc.x * sc, acc.y * sc, acc.z * sc, acc.w * sc);
}

// ---------------- HAN: semantic attention logits ----------------
__global__ void __launch_bounds__(256) k_han_node(const float* __restrict__ W1g,
                                                  const float* __restrict__ b1g,
                                                  const float* __restrict__ w2g,
                                                  int n, int zbase, int wbase) {
    __shared__ float Wsm[8192];
    __shared__ float ush[4096];
    __shared__ float bsh[128];
    __shared__ float w2sh[128];
    __shared__ float wacc[2];

    const int tid = threadIdx.x, w = tid >> 5, lane = tid & 31;
    for (int t = tid; t < 2048; t += 256) {
        int k = t >> 5, L = t & 31;
        ((float4*)Wsm)[t] = *(const float4*)(W1g + k * 128 + L * 4);
    }
    if (tid < 128) { bsh[tid] = b1g[tid]; w2sh[tid] = w2g[tid]; }
    if (tid < 2) wacc[tid] = 0.f;
    __syncthreads();

    const int rows = 2 * n;
    const int r0 = (int)blockIdx.x * 64 + w * 8;
    float* u = ush + w * 512;

    for (int t = lane; t < 512; t += 32) {
        int rr = t >> 6, d = t & 63;
        int row = r0 + rr;
        u[t] = (row < rows) ? g_z[(size_t)zbase + (size_t)row * DD + d] : 0.f;
    }
    __syncwarp();

    float acc[8][4];
#pragma unroll
    for (int a = 0; a < 8; a++) { acc[a][0] = acc[a][1] = acc[a][2] = acc[a][3] = 0.f; }

#pragma unroll 2
    for (int kk = 0; kk < 16; kk++) {
        float4 w0 = ((const float4*)Wsm)[(4 * kk + 0) * 32 + lane];
        float4 w1 = ((const float4*)Wsm)[(4 * kk + 1) * 32 + lane];
        float4 w2 = ((const float4*)Wsm)[(4 * kk + 2) * 32 + lane];
        float4 w3 = ((const float4*)Wsm)[(4 * kk + 3) * 32 + lane];
#pragma unroll
        for (int rr = 0; rr < 8; rr++) {
            float4 uv = *(const float4*)(u + rr * 64 + kk * 4);
            acc[rr][0] += uv.x * w0.x + uv.y * w1.x + uv.z * w2.x + uv.w * w3.x;
            acc[rr][1] += uv.x * w0.y + uv.y * w1.y + uv.z * w2.y + uv.w * w3.y;
            acc[rr][2] += uv.x * w0.z + uv.y * w1.z + uv.z * w2.z + uv.w * w3.z;
            acc[rr][3] += uv.x * w0.w + uv.y * w1.w + uv.z * w2.w + uv.w * w3.w;
        }
    }

    float wl01[2] = {0.f, 0.f};
#pragma unroll
    for (int rr = 0; rr < 8; rr++) {
        int row = r0 + rr;
        float wl = 0.f;
#pragma unroll
        for (int c = 0; c < 4; c++) {
            int j = lane * 4 + c;
            wl += tanhf(acc[rr][c] + bsh[j]) * w2sh[j];
        }
        if (row < rows) wl01[row & 1] += wl;
    }
#pragma unroll
    for (int off = 16; off; off >>= 1) {
        wl01[0] += __shfl_xor_sync(0xffffffffu, wl01[0], off);
        wl01[1] += __shfl_xor_sync(0xffffffffu, wl01[1], off);
    }
    if (lane == 0) {
        atomicAdd(&wacc[0], wl01[0]);
        atomicAdd(&wacc[1], wl01[1]);
    }
    __syncthreads();
    if (tid < 2) atomicAdd(&g_wsum[wbase + tid], wacc[tid]);
}

// ---------------- final combine (fused layer-2 epilogue) ----------------
__global__ void __launch_bounds__(256) k_combine(float* __restrict__ out) {
    unsigned i = blockIdx.x * 256u + threadIdx.x;
    if (i >= (unsigned)(NN * DD)) return;
    unsigned node = i >> 6, d = i & 63u;
    float w0, w1;
    size_t zr;
    if (node < NU) {
        w0 = g_wsum[0] * (1.f / NU);
        w1 = g_wsum[1] * (1.f / NU);
        zr = (size_t)node * 128;
    } else {
        w0 = g_wsum[2] * (1.f / NI);
        w1 = g_wsum[3] * (1.f / NI);
        zr = (size_t)NU * 128 + (size_t)(node - NU) * 128;
    }
    float mx = fmaxf(w0, w1);
    float e0 = __expf(w0 - mx), e1 = __expf(w1 - mx);
    float inv = 1.f / (e0 + e1);
    float han = (e0 * inv) * g_z[zr + d] + (e1 * inv) * g_z[zr + 64 + d];
    float cur0 = g_cur[i];
    float cur1 = g_curB[i];
    float cur2 = g_gnn[i] + g_int[i] + cur1;
    float total = cur0 + cur1 + cur2;
    out[i] = 0.5f * total + 0.5f * han;
}

// ---------------- launcher ----------------
extern "C" void kernel_launch(void* const* d_in, const int* in_sizes, int n_in,
                              void* d_out, int out_size) {
    const int*   G    = (const int*)d_in[0];
    const float* Gv   = (const float*)d_in[1];
    const float* fu   = (const float*)d_in[2];
    const float* fi   = (const float*)d_in[3];
    const float* Wu   = (const float*)d_in[4];
    const float* Wi   = (const float*)d_in[5];
    const int*   eu   = (const int*)d_in[6];
    const int*   ei   = (const int*)d_in[7];
    const float* suW1 = (const float*)d_in[8];
    const float* sub1 = (const float*)d_in[9];
    const float* suw2 = (const float*)d_in[10];
    const float* siW1 = (const float*)d_in[11];
    const float* sib1 = (const float*)d_in[12];
    const float* siw2 = (const float*)d_in[13];
    float* out = (float*)d_out;

    static cudaStream_t s_han = nullptr, s_int = nullptr, s_init = nullptr;
    static cudaEvent_t ev_root = nullptr, ev_zero = nullptr, ev_join = nullptr;
    static cudaEvent_t ev_init = nullptr, ev_i1 = nullptr, ev_i2 = nullptr, ev_e1 = nullptr;
    static float* p_cur = nullptr;
    static float* p_curB = nullptr;
    if (!s_han) {
        cudaStreamCreateWithFlags(&s_han, cudaStreamNonBlocking);
        cudaStreamCreateWithFlags(&s_int, cudaStreamNonBlocking);
        cudaStreamCreateWithFlags(&s_init, cudaStreamNonBlocking);
        cudaEventCreateWithFlags(&ev_root, cudaEventDisableTiming);
        cudaEventCreateWithFlags(&ev_zero, cudaEventDisableTiming);
        cudaEventCreateWithFlags(&ev_join, cudaEventDisableTiming);
        cudaEventCreateWithFlags(&ev_init, cudaEventDisableTiming);
        cudaEventCreateWithFlags(&ev_i1, cudaEventDisableTiming);
        cudaEventCreateWithFlags(&ev_i2, cudaEventDisableTiming);
        cudaEventCreateWithFlags(&ev_e1, cudaEventDisableTiming);
        cudaFuncSetAttribute(k_intent, cudaFuncAttributeMaxDynamicSharedMemorySize,
                             INTENT_SMEM);
        cudaGetSymbolAddress((void**)&p_cur, g_cur);
        cudaGetSymbolAddress((void**)&p_curB, g_curB);
    }

    const int UB = (NU + IT_ROWS_PER_BLOCK - 1) / IT_ROWS_PER_BLOCK;
    const int IB = (NI + IT_ROWS_PER_BLOCK - 1) / IT_ROWS_PER_BLOCK;

    // root fork on the capture stream
    cudaEventRecord(ev_root, 0);

    // ---- layer-1 intent on s_int: reads fu/fi directly, starts at t~0 ----
    cudaStreamWaitEvent(s_int, ev_root, 0);
    k_intent<<<UB + IB, IT_THREADS, INTENT_SMEM, s_int>>>(Wu, Wi, fu, fi);
    cudaEventRecord(ev_i1, s_int);

    // ---- init on its own stream ----
    cudaStreamWaitEvent(s_init, ev_root, 0);
    k_init<<<37500, 256, 0, s_init>>>(fu, fi);
    cudaEventRecord(ev_init, s_init);

    // ---- main: counters zero, then fork HAN ----
    k_zero_cnt<<<1172, 256>>>();
    cudaEventRecord(ev_zero, 0);

    cudaStreamWaitEvent(s_han, ev_zero, 0);
    k_histH<<<12500, 256, 0, s_han>>>(eu, EU_, NU, 0);
    k_histH<<<6250, 256, 0, s_han>>>(ei, EI_, NI, 2 * NU);
    k_scanH1<<<2 * NB_HU + 2 * NB_HI, 1024, 0, s_han>>>();
    k_scanH2<<<1, 128, 0, s_han>>>();
    k_scanH3<<<2 * NB_HU + 2 * NB_HI, 1024, 0, s_han>>>();
    k_fillH<<<12500, 256, 0, s_han>>>(eu, EU_, NU, 0, 0, 0);
    k_fillH<<<6250, 256, 0, s_han>>>(ei, EI_, NI, 2 * NU, 2 * (NU + 1), 2 * EU_);
    k_hgather<<<12500, 256, 0, s_han>>>(fu, EU_, NU, 0, 0, 0, 0);
    k_hgather<<<6250, 256, 0, s_han>>>(fi, EI_, NI, 2 * NU, 2 * (NU + 1), 2 * EU_, NU * 128);
    k_han_node<<<3125, 256, 0, s_han>>>(suW1, sub1, suw2, NU, 0, 0);
    k_han_node<<<1563, 256, 0, s_han>>>(siW1, sib1, siw2, NI, NU * 128, 2);
    cudaEventRecord(ev_join, s_han);

    // ---- main: CSR-G build + spmm1 ----
    k_histG<<<12500, 256>>>(G);
    k_scanG1<<<NB_G, 1024>>>();
    k_scanG2<<<1, 32>>>();
    k_scanG3<<<NB_G, 1024>>>();
    k_fillG<<<12500, 256>>>(G, Gv);
    cudaStreamWaitEvent(0, ev_init, 0);
    k_spmm_csr<<<9375, 256>>>(p_cur);
    cudaStreamWaitEvent(0, ev_i1, 0);
    k_epi1<<<9375, 256>>>();
    cudaEventRecord(ev_e1, 0);

    // ---- layer 2: spmm on main ∥ intent on s_int ----
    cudaStreamWaitEvent(s_int, ev_e1, 0);
    k_intent<<<UB + IB, IT_THREADS, INTENT_SMEM, s_int>>>(
        Wu, Wi, p_curB, p_curB + (size_t)NU * DD);
    cudaEventRecord(ev_i2, s_int);
    k_spmm_csr<<<9375, 256>>>(p_curB);
    cudaStreamWaitEvent(0, ev_i2, 0);

    // ---- join + combine (fused epilogue 2) ----
    cudaStreamWaitEvent(0, ev_join, 0);
    k_combine<<<37500, 256>>>(out);
}

// round 16
// speedup vs baseline: 1.1877x; 1.1877x over previous
#include <cuda_runtime.h>

#define NU 100000
#define NI 50000
#define NN 150000
#define DD 64
#define EG 3200000
#define EU_ 1600000
#define EI_ 800000

typedef unsigned long long ull;

// ---------------- device scratch ----------------
__device__ float g_cur[NN * DD];    // cur0 = emb
__device__ float g_curB[NN * DD];   // cur1 after layer 1
__device__ float g_gnn[NN * DD];
__device__ float g_int[NN * DD];
__device__ float g_z[NN * 2 * DD];
__device__ float g_wsum[4];

// CSR for G
__device__ int    g_cntG[NN];
__device__ int    g_curG[NN];
__device__ int    g_rptrG[NN + 1];
__device__ float2 g_epayG[EG];

// CSR + degrees for HAN
#define HN (2 * NU + 2 * NI)
__device__ int g_dout[HN];
__device__ int g_din[HN];
__device__ int g_curH[HN];
__device__ int g_rptrH[2 * (NU + 1) + 2 * (NI + 1)];
__device__ int g_hpay[2 * EU_ + 2 * EI_];

// block-sum scratch for parallel scans
#define NB_G 147
#define NB_HU 98
#define NB_HI 49
__device__ int g_bsumG[NB_G];
__device__ int g_bsumH[4 * NB_HU];

// f32x2 packed math (sm_100+)
__device__ __forceinline__ ull pk2(float a) {
    ull r;
    asm("mov.b64 %0, {%1, %1};" : "=l"(r) : "f"(a));
    return r;
}
__device__ __forceinline__ ull pack2(float lo, float hi) {
    ull r;
    asm("mov.b64 %0, {%1, %2};" : "=l"(r) : "f"(lo), "f"(hi));
    return r;
}
__device__ __forceinline__ void fma2(ull& d, ull a, ull b) {
    asm("fma.rn.f32x2 %0, %1, %2, %0;" : "+l"(d) : "l"(a), "l"(b));
}
__device__ __forceinline__ float2 up2(ull v) {
    float2 f;
    asm("mov.b64 {%0, %1}, %2;" : "=f"(f.x), "=f"(f.y) : "l"(v));
    return f;
}

// ---------------- zero counters ----------------
__global__ void __launch_bounds__(256) k_zero_cnt() {
    unsigned i = blockIdx.x * 256u + threadIdx.x;
    if (i < NN) { g_cntG[i] = 0; g_curG[i] = 0; }
    if (i < HN) { g_dout[i] = 0; g_din[i] = 0; g_curH[i] = 0; }
    if (i < 4u) g_wsum[i] = 0.f;
}

// ---------------- init (cur0 only) ----------------
__global__ void __launch_bounds__(256) k_init(const float* __restrict__ fu,
                                              const float* __restrict__ fi) {
    unsigned i = blockIdx.x * 256u + threadIdx.x;
    if (i < NU * DD) g_cur[i] = fu[i];
    else if (i < NN * DD) g_cur[i] = fi[i - NU * DD];
}

// ---------------- histograms ----------------
__global__ void __launch_bounds__(256) k_histG(const int* __restrict__ G) {
    unsigned e = blockIdx.x * 256u + threadIdx.x;
    if (e >= EG) return;
    atomicAdd(&g_cntG[__ldg(G + e)], 1);
}

__global__ void __launch_bounds__(256) k_histH(const int* __restrict__ edges, int E2,
                                               int n, int base) {
    unsigned t = blockIdx.x * 256u + threadIdx.x;
    if (t >= 2u * (unsigned)E2) return;
    int m = (t >= (unsigned)E2) ? 1 : 0;
    int e = (int)t - m * E2;
    int src = __ldg(edges + (size_t)m * 2 * E2 + e);
    int dst = __ldg(edges + (size_t)m * 2 * E2 + E2 + e);
    atomicAdd(&g_dout[base + m * n + src], 1);
    atomicAdd(&g_din[base + m * n + dst], 1);
}

// ---------------- parallel scans ----------------
__device__ __forceinline__ int blockscan_1024(int v, int* ws) {
    const int tid = threadIdx.x, lane = tid & 31, wid = tid >> 5;
    int x = v;
#pragma unroll
    for (int off = 1; off < 32; off <<= 1) {
        int y = __shfl_up_sync(0xffffffffu, x, off);
        if (lane >= off) x += y;
    }
    if (lane == 31) ws[wid] = x;
    __syncthreads();
    if (wid == 0) {
        int s = ws[lane];
#pragma unroll
        for (int off = 1; off < 32; off <<= 1) {
            int y = __shfl_up_sync(0xffffffffu, s, off);
            if (lane >= off) s += y;
        }
        ws[lane] = s;
    }
    __syncthreads();
    return x - v + (wid > 0 ? ws[wid - 1] : 0);
}

__global__ void __launch_bounds__(1024) k_scanG1() {
    __shared__ int ws[32];
    int i = blockIdx.x * 1024 + threadIdx.x;
    int v = (i < NN) ? g_cntG[i] : 0;
    int excl = blockscan_1024(v, ws);
    if (i < NN) g_rptrG[i] = excl;
    if (threadIdx.x == 0) g_bsumG[blockIdx.x] = ws[31];
}

__global__ void __launch_bounds__(32) k_scanG2() {
    int lane = threadIdx.x;
    int carry = 0;
    for (int base = 0; base < NB_G; base += 32) {
        int idx = base + lane;
        int v = (idx < NB_G) ? g_bsumG[idx] : 0;
        int x = v;
#pragma unroll
        for (int off = 1; off < 32; off <<= 1) {
            int y = __shfl_up_sync(0xffffffffu, x, off);
            if (lane >= off) x += y;
        }
        if (idx < NB_G) g_bsumG[idx] = x - v + carry;
        carry += __shfl_sync(0xffffffffu, x, 31);
    }
    if (lane == 0) g_rptrG[NN] = carry;
}

__global__ void __launch_bounds__(1024) k_scanG3() {
    int i = blockIdx.x * 1024 + threadIdx.x;
    if (i < NN) g_rptrG[i] += g_bsumG[blockIdx.x];
}

__device__ __forceinline__ void hseg_decode(int b, int& seg, int& lb, int& n,
                                            const int*& cnt, int*& rptr) {
    if (b < NB_HU)           { seg = 0; lb = b; }
    else if (b < 2 * NB_HU)  { seg = 1; lb = b - NB_HU; }
    else if (b < 2 * NB_HU + NB_HI) { seg = 2; lb = b - 2 * NB_HU; }
    else                     { seg = 3; lb = b - 2 * NB_HU - NB_HI; }
    n = (seg < 2) ? NU : NI;
    cnt = g_din + (seg == 0 ? 0 : seg == 1 ? NU : seg == 2 ? 2 * NU : 2 * NU + NI);
    rptr = g_rptrH + (seg == 0 ? 0 : seg == 1 ? (NU + 1)
                      : seg == 2 ? 2 * (NU + 1) : 2 * (NU + 1) + (NI + 1));
}

__global__ void __launch_bounds__(1024) k_scanH1() {
    __shared__ int ws[32];
    int seg, lb, n; const int* cnt; int* rptr;
    hseg_decode(blockIdx.x, seg, lb, n, cnt, rptr);
    int i = lb * 1024 + threadIdx.x;
    int v = (i < n) ? cnt[i] : 0;
    int excl = blockscan_1024(v, ws);
    if (i < n) rptr[i] = excl;
    if (threadIdx.x == 0) g_bsumH[seg * NB_HU + lb] = ws[31];
}

__global__ void __launch_bounds__(128) k_scanH2() {
    int lane = threadIdx.x & 31, seg = threadIdx.x >> 5;
    int nb = (seg < 2) ? NB_HU : NB_HI;
    int n = (seg < 2) ? NU : NI;
    int* rptr = g_rptrH + (seg == 0 ? 0 : seg == 1 ? (NU + 1)
                           : seg == 2 ? 2 * (NU + 1) : 2 * (NU + 1) + (NI + 1));
    int* bs = g_bsumH + seg * NB_HU;
    int carry = 0;
    for (int base = 0; base < nb; base += 32) {
        int idx = base + lane;
        int v = (idx < nb) ? bs[idx] : 0;
        int x = v;
#pragma unroll
        for (int off = 1; off < 32; off <<= 1) {
            int y = __shfl_up_sync(0xffffffffu, x, off);
            if (lane >= off) x += y;
        }
        if (idx < nb) bs[idx] = x - v + carry;
        carry += __shfl_sync(0xffffffffu, x, 31);
    }
    if (lane == 0) rptr[n] = carry;
}

__global__ void __launch_bounds__(1024) k_scanH3() {
    int seg, lb, n; const int* cnt; int* rptr;
    hseg_decode(blockIdx.x, seg, lb, n, cnt, rptr);
    int i = lb * 1024 + threadIdx.x;
    if (i < n) rptr[i] += g_bsumH[seg * NB_HU + lb];
}

// ---------------- CSR fill ----------------
__global__ void __launch_bounds__(256) k_fillG(const int* __restrict__ G,
                                               const float* __restrict__ gv) {
    unsigned e = blockIdx.x * 256u + threadIdx.x;
    if (e >= EG) return;
    int row = __ldg(G + e);
    int col = __ldg(G + EG + e);
    float v = __ldg(gv + e);
    int pos = g_rptrG[row] + atomicAdd(&g_curG[row], 1);
    g_epayG[pos] = make_float2(__int_as_float(col), v);
}

__global__ void __launch_bounds__(256) k_fillH(const int* __restrict__ edges, int E2,
                                               int n, int base, int rbase, int paybase) {
    unsigned t = blockIdx.x * 256u + threadIdx.x;
    if (t >= 2u * (unsigned)E2) return;
    int m = (t >= (unsigned)E2) ? 1 : 0;
    int e = (int)t - m * E2;
    int src = __ldg(edges + (size_t)m * 2 * E2 + e);
    int dst = __ldg(edges + (size_t)m * 2 * E2 + E2 + e);
    const int* rptr = g_rptrH + rbase + m * (n + 1);
    int pos = rptr[dst] + atomicAdd(&g_curH[base + m * n + dst], 1);
    g_hpay[paybase + m * E2 + pos] = src;
}

// ---------------- DCCF: CSR SpMM (src-parameterized) ----------------
__global__ void __launch_bounds__(256) k_spmm_csr(const float* __restrict__ src) {
    unsigned t = blockIdx.x * 256u + threadIdx.x;
    unsigned r = t >> 4;
    unsigned c = t & 15u;
    if (r >= NN) return;
    int s = g_rptrG[r], e = g_rptrG[r + 1];
    float4 acc = make_float4(0.f, 0.f, 0.f, 0.f);
    int i = s;
    for (; i + 2 <= e; i += 2) {
        float2 p0 = __ldg(&g_epayG[i]);
        float2 p1 = __ldg(&g_epayG[i + 1]);
        int c0 = __float_as_int(p0.x), c1 = __float_as_int(p1.x);
        float4 x0 = *(const float4*)(src + (size_t)c0 * DD + c * 4);
        float4 x1 = *(const float4*)(src + (size_t)c1 * DD + c * 4);
        acc.x += p0.y * x0.x + p1.y * x1.x;
        acc.y += p0.y * x0.y + p1.y * x1.y;
        acc.z += p0.y * x0.z + p1.y * x1.z;
        acc.w += p0.y * x0.w + p1.y * x1.w;
    }
    if (i < e) {
        float2 p0 = __ldg(&g_epayG[i]);
        int c0 = __float_as_int(p0.x);
        float4 x0 = *(const float4*)(src + (size_t)c0 * DD + c * 4);
        acc.x += p0.y * x0.x; acc.y += p0.y * x0.y;
        acc.z += p0.y * x0.z; acc.w += p0.y * x0.w;
    }
    *(float4*)(g_gnn + (size_t)r * DD + c * 4) = acc;
}

// ---------------- DCCF: intent projection — R14 version (float2 WTp, 2 CTA/SM) ----------------
#define INTENT_SMEM 82944
#define IT_THREADS 256
#define IT_ROWS_PER_BLOCK 64

__global__ void __launch_bounds__(IT_THREADS, 2)
k_intent(const float* __restrict__ Wu, const float* __restrict__ Wi,
         const float* __restrict__ srcu, const float* __restrict__ srci) {
    extern __shared__ float sm[];
    float2* WTpw = (float2*)sm;
    const float2* WTp = (const float2*)sm;
    const int tid = threadIdx.x, w = tid >> 5, lane = tid & 31;

    ull* uT2 = (ull*)(sm + 8448) + w * 256;
    ull* pT2 = (ull*)(sm + 12544) + w * 512;

    const int UB = (NU + IT_ROWS_PER_BLOCK - 1) / IT_ROWS_PER_BLOCK;
    const bool isUser = (int)blockIdx.x < UB;
    const float* Wg = isUser ? Wu : Wi;
    const int rowbase = isUser ? (int)blockIdx.x * IT_ROWS_PER_BLOCK
                               : NU + ((int)blockIdx.x - UB) * IT_ROWS_PER_BLOCK;
    const int rowlim = isUser ? NU : NN;
    const float* srcp = isUser ? srcu : srci;
    const int srcoff = isUser ? 0 : NU;

    for (int t = tid; t < 4096; t += IT_THREADS) {
        int L = t >> 7, j = t & 127;
        WTpw[j * 33 + L] = make_float2(Wg[(2 * L) * 128 + j], Wg[(2 * L + 1) * 128 + j]);
    }
    __syncthreads();

    const int r0 = rowbase + w * 8;

    for (int t = lane; t < 256; t += 32) {
        int rho = t >> 6, k = t & 63;
        int ra = r0 + 2 * rho, rb = ra + 1;
        float xa = (ra < rowlim) ? srcp[(size_t)(ra - srcoff) * DD + k] : 0.f;
        float xb = (rb < rowlim) ? srcp[(size_t)(rb - srcoff) * DD + k] : 0.f;
        uT2[rho * 64 + k] = pack2(xa, xb);
    }
    __syncwarp();

    ull acc[4][4];
#pragma unroll
    for (int a = 0; a < 4; a++) { acc[a][0] = acc[a][1] = acc[a][2] = acc[a][3] = 0ull; }

    const ulonglong2* uT2v = (const ulonglong2*)uT2;
#pragma unroll 4
    for (int L = 0; L < 32; L++) {
        float2 w0 = WTp[(lane +  0) * 33 + L];
        float2 w1 = WTp[(lane + 32) * 33 + L];
        float2 w2 = WTp[(lane + 64) * 33 + L];
        float2 w3 = WTp[(lane + 96) * 33 + L];
        ull s0x = pk2(w0.x), s0y = pk2(w0.y);
        ull s1x = pk2(w1.x), s1y = pk2(w1.y);
        ull s2x = pk2(w2.x), s2y = pk2(w2.y);
        ull s3x = pk2(w3.x), s3y = pk2(w3.y);
#pragma unroll
        for (int rho = 0; rho < 4; rho++) {
            ulonglong2 up = uT2v[rho * 32 + L];
            fma2(acc[rho][0], s0x, up.x); fma2(acc[rho][0], s0y, up.y);
            fma2(acc[rho][1], s1x, up.x); fma2(acc[rho][1], s1y, up.y);
            fma2(acc[rho][2], s2x, up.x); fma2(acc[rho][2], s2y, up.y);
            fma2(acc[rho][3], s3x, up.x); fma2(acc[rho][3], s3y, up.y);
        }
    }

#pragma unroll
    for (int rho = 0; rho < 4; rho++) {
        float2 a0 = up2(acc[rho][0]), a1 = up2(acc[rho][1]);
        float2 a2 = up2(acc[rho][2]), a3 = up2(acc[rho][3]);
        float ml = fmaxf(fmaxf(a0.x, a1.x), fmaxf(a2.x, a3.x));
        float mh = fmaxf(fmaxf(a0.y, a1.y), fmaxf(a2.y, a3.y));
#pragma unroll
        for (int off = 16; off; off >>= 1) {
            ml = fmaxf(ml, __shfl_xor_sync(0xffffffffu, ml, off));
            mh = fmaxf(mh, __shfl_xor_sync(0xffffffffu, mh, off));
        }
        float el0 = __expf(a0.x - ml), el1 = __expf(a1.x - ml);
        float el2 = __expf(a2.x - ml), el3 = __expf(a3.x - ml);
        float eh0 = __expf(a0.y - mh), eh1 = __expf(a1.y - mh);
        float eh2 = __expf(a2.y - mh), eh3 = __expf(a3.y - mh);
        float sl = el0 + el1 + el2 + el3;
        float sh = eh0 + eh1 + eh2 + eh3;
#pragma unroll
        for (int off = 16; off; off >>= 1) {
            sl += __shfl_xor_sync(0xffffffffu, sl, off);
            sh += __shfl_xor_sync(0xffffffffu, sh, off);
        }
        float il = 1.f / sl, ih = 1.f / sh;
        pT2[rho * 128 + lane +  0] = pack2(el0 * il, eh0 * ih);
        pT2[rho * 128 + lane + 32] = pack2(el1 * il, eh1 * ih);
        pT2[rho * 128 + lane + 64] = pack2(el2 * il, eh2 * ih);
        pT2[rho * 128 + lane + 96] = pack2(el3 * il, eh3 * ih);
    }
    __syncwarp();

    ull acc2[4][2];
#pragma unroll
    for (int a = 0; a < 4; a++) { acc2[a][0] = 0ull; acc2[a][1] = 0ull; }

    const ulonglong2* pT2v = (const ulonglong2*)pT2;
#pragma unroll 2
    for (int j4 = 0; j4 < 32; j4++) {
        ulonglong2 P0a = pT2v[0 * 64 + 2 * j4], P0b = pT2v[0 * 64 + 2 * j4 + 1];
        ulonglong2 P1a = pT2v[1 * 64 + 2 * j4], P1b = pT2v[1 * 64 + 2 * j4 + 1];
        ulonglong2 P2a = pT2v[2 * 64 + 2 * j4], P2b = pT2v[2 * 64 + 2 * j4 + 1];
        ulonglong2 P3a = pT2v[3 * 64 + 2 * j4], P3b = pT2v[3 * 64 + 2 * j4 + 1];
#define P2J(JJ, PW)                                             \
        {                                                       \
            float2 wt = WTp[(4 * j4 + JJ) * 33 + lane];         \
            ull s0 = pk2(wt.x), s1 = pk2(wt.y);                 \
            fma2(acc2[0][0], s0, P0##PW); fma2(acc2[0][1], s1, P0##PW); \
            fma2(acc2[1][0], s0, P1##PW); fma2(acc2[1][1], s1, P1##PW); \
            fma2(acc2[2][0], s0, P2##PW); fma2(acc2[2][1], s1, P2##PW); \
            fma2(acc2[3][0], s0, P3##PW); fma2(acc2[3][1], s1, P3##PW); \
        }
        P2J(0, a.x) P2J(1, a.y) P2J(2, b.x) P2J(3, b.y)
#undef P2J
    }

#pragma unroll
    for (int rho = 0; rho < 4; rho++) {
        float2 o0 = up2(acc2[rho][0]);
        float2 o1 = up2(acc2[rho][1]);
#pragma unroll
        for (int par = 0; par < 2; par++) {
            int r = r0 + 2 * rho + par;
            if (r >= rowlim) continue;
            float oa = par ? o0.y : o0.x;
            float ob = par ? o1.y : o1.x;
            *(float2*)(g_int + (size_t)r * DD + lane * 2) = make_float2(oa, ob);
        }
    }
}

// ---------------- DCCF: layer-1 epilogue: curB = gnn + int + cur0 ----------------
__global__ void __launch_bounds__(256) k_epi1() {
    unsigned i = blockIdx.x * 256u + threadIdx.x;
    if (i >= (unsigned)(NN * DD / 4)) return;
    float4 gn = ((const float4*)g_gnn)[i];
    float4 iv = ((const float4*)g_int)[i];
    float4 cu = ((const float4*)g_cur)[i];
    float4 nv;
    nv.x = gn.x + iv.x + cu.x;
    nv.y = gn.y + iv.y + cu.y;
    nv.z = gn.z + iv.z + cu.z;
    nv.w = gn.w + iv.w + cu.w;
    ((float4*)g_curB)[i] = nv;
}

// ---------------- HAN: CSR gather ----------------
__global__ void __launch_bounds__(256) k_hgather(const float* __restrict__ feat, int E2,
                                                 int n, int base, int rbase, int paybase,
                                                 int zbase) {
    unsigned t = blockIdx.x * 256u + threadIdx.x;
    unsigned idx = t >> 4;
    unsigned c = t & 15u;
    if (idx >= 2u * (unsigned)n) return;
    int m = (idx >= (unsigned)n) ? 1 : 0;
    int node = (int)idx - m * n;
    const int* rptr = g_rptrH + rbase + m * (n + 1);
    int s = rptr[node], e = rptr[node + 1];
    const int* pay = g_hpay + paybase + m * E2;
    const int* dout = g_dout + base + m * n;
    float4 acc = make_float4(0.f, 0.f, 0.f, 0.f);
    int i = s;
    for (; i + 2 <= e; i += 2) {
        int s0 = __ldg(pay + i), s1 = __ldg(pay + i + 1);
        float w0 = rsqrtf((float)__ldg(dout + s0));
        float w1 = rsqrtf((float)__ldg(dout + s1));
        float4 x0 = *(const float4*)(feat + (size_t)s0 * DD + c * 4);
        float4 x1 = *(const float4*)(feat + (size_t)s1 * DD + c * 4);
        acc.x += w0 * x0.x + w1 * x1.x;
        acc.y += w0 * x0.y + w1 * x1.y;
        acc.z += w0 * x0.z + w1 * x1.z;
        acc.w += w0 * x0.w + w1 * x1.w;
    }
    if (i < e) {
        int s0 = __ldg(pay + i);
        float w0 = rsqrtf((float)__ldg(dout + s0));
        float4 x0 = *(const float4*)(feat + (size_t)s0 * DD + c * 4);
        acc.x += w0 * x0.x; acc.y += w0 * x0.y;
        acc.z += w0 * x0.z; acc.w += w0 * x0.w;
    }
    float din = (float)(e - s);
    float sc = (din > 0.f) ? rsqrtf(din) : 0.f;
    *(float4*)(g_z + (size_t)zbase + ((size_t)node * 2 + m) * DD + c * 4) =
        make_float4(acc.x * sc, acc.y * sc, acc.z * sc, acc.w * sc);
}

// ---------------- HAN: semantic attention logits ----------------
__global__ void __launch_bounds__(256) k_han_node(const float* __restrict__ W1g,
                                                  const float* __restrict__ b1g,
                                                  const float* __restrict__ w2g,
                                                  int n, int zbase, int wbase) {
    __shared__ float Wsm[8192];
    __shared__ float ush[4096];
    __shared__ float bsh[128];
    __shared__ float w2sh[128];
    __shared__ float wacc[2];

    const int tid = threadIdx.x, w = tid >> 5, lane = tid & 31;
    for (int t = tid; t < 2048; t += 256) {
        int k = t >> 5, L = t & 31;
        ((float4*)Wsm)[t] = *(const float4*)(W1g + k * 128 + L * 4);
    }
    if (tid < 128) { bsh[tid] = b1g[tid]; w2sh[tid] = w2g[tid]; }
    if (tid < 2) wacc[tid] = 0.f;
    __syncthreads();

    const int rows = 2 * n;
    const int r0 = (int)blockIdx.x * 64 + w * 8;
    float* u = ush + w * 512;

    for (int t = lane; t < 512; t += 32) {
        int rr = t >> 6, d = t & 63;
        int row = r0 + rr;
        u[t] = (row < rows) ? g_z[(size_t)zbase + (size_t)row * DD + d] : 0.f;
    }
    __syncwarp();

    float acc[8][4];
#pragma unroll
    for (int a = 0; a < 8; a++) { acc[a][0] = acc[a][1] = acc[a][2] = acc[a][3] = 0.f; }

#pragma unroll 2
    for (int kk = 0; kk < 16; kk++) {
        float4 w0 = ((const float4*)Wsm)[(4 * kk + 0) * 32 + lane];
        float4 w1 = ((const float4*)Wsm)[(4 * kk + 1) * 32 + lane];
        float4 w2 = ((const float4*)Wsm)[(4 * kk + 2) * 32 + lane];
        float4 w3 = ((const float4*)Wsm)[(4 * kk + 3) * 32 + lane];
#pragma unroll
        for (int rr = 0; rr < 8; rr++) {
            float4 uv = *(const float4*)(u + rr * 64 + kk * 4);
            acc[rr][0] += uv.x * w0.x + uv.y * w1.x + uv.z * w2.x + uv.w * w3.x;
            acc[rr][1] += uv.x * w0.y + uv.y * w1.y + uv.z * w2.y + uv.w * w3.y;
            acc[rr][2] += uv.x * w0.z + uv.y * w1.z + uv.z * w2.z + uv.w * w3.z;
            acc[rr][3] += uv.x * w0.w + uv.y * w1.w + uv.z * w2.w + uv.w * w3.w;
        }
    }

    float wl01[2] = {0.f, 0.f};
#pragma unroll
    for (int rr = 0; rr < 8; rr++) {
        int row = r0 + rr;
        float wl = 0.f;
#pragma unroll
        for (int c = 0; c < 4; c++) {
            int j = lane * 4 + c;
            wl += tanhf(acc[rr][c] + bsh[j]) * w2sh[j];
        }
        if (row < rows) wl01[row & 1] += wl;
    }
#pragma unroll
    for (int off = 16; off; off >>= 1) {
        wl01[0] += __shfl_xor_sync(0xffffffffu, wl01[0], off);
        wl01[1] += __shfl_xor_sync(0xffffffffu, wl01[1], off);
    }
    if (lane == 0) {
        atomicAdd(&wacc[0], wl01[0]);
        atomicAdd(&wacc[1], wl01[1]);
    }
    __syncthreads();
    if (tid < 2) atomicAdd(&g_wsum[wbase + tid], wacc[tid]);
}

// ---------------- final combine (fused layer-2 epilogue) ----------------
__global__ void __launch_bounds__(256) k_combine(float* __restrict__ out) {
    unsigned i = blockIdx.x * 256u + threadIdx.x;
    if (i >= (unsigned)(NN * DD)) return;
    unsigned node = i >> 6, d = i & 63u;
    float w0, w1;
    size_t zr;
    if (node < NU) {
        w0 = g_wsum[0] * (1.f / NU);
        w1 = g_wsum[1] * (1.f / NU);
        zr = (size_t)node * 128;
    } else {
        w0 = g_wsum[2] * (1.f / NI);
        w1 = g_wsum[3] * (1.f / NI);
        zr = (size_t)NU * 128 + (size_t)(node - NU) * 128;
    }
    float mx = fmaxf(w0, w1);
    float e0 = __expf(w0 - mx), e1 = __expf(w1 - mx);
    float inv = 1.f / (e0 + e1);
    float han = (e0 * inv) * g_z[zr + d] + (e1 * inv) * g_z[zr + 64 + d];
    float cur0 = g_cur[i];
    float cur1 = g_curB[i];
    float cur2 = g_gnn[i] + g_int[i] + cur1;
    float total = cur0 + cur1 + cur2;
    out[i] = 0.5f * total + 0.5f * han;
}

// ---------------- launcher ----------------
extern "C" void kernel_launch(void* const* d_in, const int* in_sizes, int n_in,
                              void* d_out, int out_size) {
    const int*   G    = (const int*)d_in[0];
    const float* Gv   = (const float*)d_in[1];
    const float* fu   = (const float*)d_in[2];
    const float* fi   = (const float*)d_in[3];
    const float* Wu   = (const float*)d_in[4];
    const float* Wi   = (const float*)d_in[5];
    const int*   eu   = (const int*)d_in[6];
    const int*   ei   = (const int*)d_in[7];
    const float* suW1 = (const float*)d_in[8];
    const float* sub1 = (const float*)d_in[9];
    const float* suw2 = (const float*)d_in[10];
    const float* siW1 = (const float*)d_in[11];
    const float* sib1 = (const float*)d_in[12];
    const float* siw2 = (const float*)d_in[13];
    float* out = (float*)d_out;

    static cudaStream_t s_han = nullptr, s_int = nullptr, s_init = nullptr;
    static cudaEvent_t ev_root = nullptr, ev_zero = nullptr, ev_join = nullptr;
    static cudaEvent_t ev_init = nullptr, ev_i1 = nullptr, ev_i2 = nullptr, ev_e1 = nullptr;
    static float* p_cur = nullptr;
    static float* p_curB = nullptr;
    if (!s_han) {
        cudaStreamCreateWithFlags(&s_han, cudaStreamNonBlocking);
        cudaStreamCreateWithFlags(&s_int, cudaStreamNonBlocking);
        cudaStreamCreateWithFlags(&s_init, cudaStreamNonBlocking);
        cudaEventCreateWithFlags(&ev_root, cudaEventDisableTiming);
        cudaEventCreateWithFlags(&ev_zero, cudaEventDisableTiming);
        cudaEventCreateWithFlags(&ev_join, cudaEventDisableTiming);
        cudaEventCreateWithFlags(&ev_init, cudaEventDisableTiming);
        cudaEventCreateWithFlags(&ev_i1, cudaEventDisableTiming);
        cudaEventCreateWithFlags(&ev_i2, cudaEventDisableTiming);
        cudaEventCreateWithFlags(&ev_e1, cudaEventDisableTiming);
        cudaFuncSetAttribute(k_intent, cudaFuncAttributeMaxDynamicSharedMemorySize,
                             INTENT_SMEM);
        cudaGetSymbolAddress((void**)&p_cur, g_cur);
        cudaGetSymbolAddress((void**)&p_curB, g_curB);
    }

    const int UB = (NU + IT_ROWS_PER_BLOCK - 1) / IT_ROWS_PER_BLOCK;
    const int IB = (NI + IT_ROWS_PER_BLOCK - 1) / IT_ROWS_PER_BLOCK;

    // root fork on the capture stream
    cudaEventRecord(ev_root, 0);

    // ---- layer-1 intent on s_int: reads fu/fi directly, starts at t~0 ----
    cudaStreamWaitEvent(s_int, ev_root, 0);
    k_intent<<<UB + IB, IT_THREADS, INTENT_SMEM, s_int>>>(Wu, Wi, fu, fi);
    cudaEventRecord(ev_i1, s_int);

    // ---- init on its own stream ----
    cudaStreamWaitEvent(s_init, ev_root, 0);
    k_init<<<37500, 256, 0, s_init>>>(fu, fi);
    cudaEventRecord(ev_init, s_init);

    // ---- main: counters zero, then fork HAN ----
    k_zero_cnt<<<1172, 256>>>();
    cudaEventRecord(ev_zero, 0);

    cudaStreamWaitEvent(s_han, ev_zero, 0);
    k_histH<<<12500, 256, 0, s_han>>>(eu, EU_, NU, 0);
    k_histH<<<6250, 256, 0, s_han>>>(ei, EI_, NI, 2 * NU);
    k_scanH1<<<2 * NB_HU + 2 * NB_HI, 1024, 0, s_han>>>();
    k_scanH2<<<1, 128, 0, s_han>>>();
    k_scanH3<<<2 * NB_HU + 2 * NB_HI, 1024, 0, s_han>>>();
    k_fillH<<<12500, 256, 0, s_han>>>(eu, EU_, NU, 0, 0, 0);
    k_fillH<<<6250, 256, 0, s_han>>>(ei, EI_, NI, 2 * NU, 2 * (NU + 1), 2 * EU_);
    k_hgather<<<12500, 256, 0, s_han>>>(fu, EU_, NU, 0, 0, 0, 0);
    k_hgather<<<6250, 256, 0, s_han>>>(fi, EI_, NI, 2 * NU, 2 * (NU + 1), 2 * EU_, NU * 128);
    k_han_node<<<3125, 256, 0, s_han>>>(suW1, sub1, suw2, NU, 0, 0);
    k_han_node<<<1563, 256, 0, s_han>>>(siW1, sib1, siw2, NI, NU * 128, 2);
    cudaEventRecord(ev_join, s_han);

    // ---- main: CSR-G build + spmm1 ----
    k_histG<<<12500, 256>>>(G);
    k_scanG1<<<NB_G, 1024>>>();
    k_scanG2<<<1, 32>>>();
    k_scanG3<<<NB_G, 1024>>>();
    k_fillG<<<12500, 256>>>(G, Gv);
    cudaStreamWaitEvent(0, ev_init, 0);
    k_spmm_csr<<<9375, 256>>>(p_cur);
    cudaStreamWaitEvent(0, ev_i1, 0);
    k_epi1<<<9375, 256>>>();
    cudaEventRecord(ev_e1, 0);

    // ---- layer 2: spmm on main ∥ intent on s_int ----
    cudaStreamWaitEvent(s_int, ev_e1, 0);
    k_intent<<<UB + IB, IT_THREADS, INTENT_SMEM, s_int>>>(
        Wu, Wi, p_curB, p_curB + (size_t)NU * DD);
    cudaEventRecord(ev_i2, s_int);
    k_spmm_csr<<<9375, 256>>>(p_curB);
    cudaStreamWaitEvent(0, ev_i2, 0);

    // ---- join + combine (fused epilogue 2) ----
    cudaStreamWaitEvent(0, ev_join, 0);
    k_combine<<<37500, 256>>>(out);
}